// round 14
// baseline (speedup 1.0000x reference)
#include <cuda_runtime.h>
#include <math.h>
#include <stdint.h>

// out = LayerNorm(Re(FFT(x, axis=-1))), x: (4,4096,2048) fp32.
// Pack z[n] = x[2n] + i x[2n+1] (1024 complex). 4-step CT: 1024 = 32 x 32,
// one WARP per row, 32 complex per lane:
//   r[j] = z[u + 32 j]; stats first (Parseval):
//     var = 0.5*(sum x^2 + sum x[c]x[(2048-c)%2048]) - x[0]^2, warp reduce
//   FFT32 over j (regs)  -> A[k1] at r[brev5(k1)]
//   r *= W_1024^{u*k1}   (register recurrence from sincospif(u/512))
//   smem transpose (pad 33) -> lane u = k1, n2 natural
//   FFT32 over n2 -> r[i] = Z[u + 32*brev5(i)]
//   untangle in natural k1 order (uk recurrence from sincospif(u/1024), x W32):
//     y[k] = ReE + cos(pi k/1024) ReO + sin(pi k/1024) ImO
//   scale+store direct: out[k], out[2048-k]; y[1024] = ReZ0 - ImZ0 (lane 0)
// No table kernel, no __syncthreads: warps fully independent.

#define ROWS 16384
#define CDIM 2048
#define EPS  1e-5f
#define FULL 0xffffffffu

__device__ __forceinline__ float2 cmul(float2 a, float2 b) {
    return make_float2(fmaf(a.x, b.x, -a.y * b.y), fmaf(a.x, b.y, a.y * b.x));
}

__host__ __device__ constexpr int brev5(int i) {
    return ((i & 1) << 4) | ((i & 2) << 2) | (i & 4) | ((i & 8) >> 2) | ((i & 16) >> 4);
}

// 32-pt DIF FFT (Gentleman-Sande), output bit-reversed: r[i] = X[brev5(i)].
__device__ __forceinline__ void fft32(float2* r) {
    const float CR[16] = { 1.0f, 0.98078528f, 0.92387953f, 0.83146961f,
                           0.70710678f, 0.55557023f, 0.38268343f, 0.19509032f,
                           0.0f, -0.19509032f, -0.38268343f, -0.55557023f,
                           -0.70710678f, -0.83146961f, -0.92387953f, -0.98078528f };
    const float CI[16] = { 0.0f, -0.19509032f, -0.38268343f, -0.55557023f,
                           -0.70710678f, -0.83146961f, -0.92387953f, -0.98078528f,
                           -1.0f, -0.98078528f, -0.92387953f, -0.83146961f,
                           -0.70710678f, -0.55557023f, -0.38268343f, -0.19509032f };
    #pragma unroll
    for (int half = 16; half >= 1; half >>= 1) {
        #pragma unroll
        for (int g = 0; g < 32; g += 2 * half) {
            #pragma unroll
            for (int j = 0; j < half; j++) {
                float2 a = r[g + j], b = r[g + j + half];
                r[g + j] = make_float2(a.x + b.x, a.y + b.y);
                float dx = a.x - b.x, dy = a.y - b.y;
                int tw = j * (16 / half);
                if (tw == 0) r[g + j + half] = make_float2(dx, dy);
                else r[g + j + half] = make_float2(fmaf(dx, CR[tw], -dy * CI[tw]),
                                                   fmaf(dx, CI[tw],  dy * CR[tw]));
            }
        }
    }
}

__global__ void __launch_bounds__(128, 4) fft_ln_kernel(const float* __restrict__ x,
                                                        const float* __restrict__ gamma,
                                                        const float* __restrict__ beta,
                                                        float* __restrict__ out) {
    __shared__ float Sx[4][33 * 32];
    __shared__ float Sy[4][33 * 32];

    const int t = threadIdx.x;
    const int w = t >> 5;
    const int u = t & 31;
    const int row = blockIdx.x * 4 + w;
    const float2* z = (const float2*)(x + (size_t)row * CDIM);

    float2 r[32];
    #pragma unroll
    for (int j = 0; j < 32; j++) r[j] = z[u + 32 * j];
    const float mu = __shfl_sync(FULL, r[0].x, 0);

    // ---- stats first: v = sum x^2 + sum x[c] x[(2048-c)&2047]
    const int pux = (32 - u) & 31;
    const int puy = 31 - u;
    float v = 0.0f;
    #pragma unroll
    for (int j = 0; j < 32; j++)
        v += r[j].x * r[j].x + r[j].y * r[j].y;
    #pragma unroll
    for (int j = 0; j < 32; j++) {
        float ax = __shfl_sync(FULL, r[31 - j].x, pux);
        float ay = __shfl_sync(FULL, r[31 - j].y, puy);
        if (u == 0) ax = r[(32 - j) & 31].x;
        v += fmaf(r[j].x, ax, r[j].y * ay);
    }
    #pragma unroll
    for (int o = 16; o > 0; o >>= 1) v += __shfl_xor_sync(FULL, v, o);
    const float rs = rsqrtf(0.5f * v - mu * mu + EPS);

    // ---- first FFT
    fft32(r);

    // ---- twiddle r[brev5(c)] *= W_1024^{u*c}; wstep = exp(-i pi u/512)
    {
        float s, c;
        sincospif((float)u * (1.0f / 512.0f), &s, &c);
        float2 wstep = make_float2(c, -s);
        float2 w2 = cmul(wstep, wstep);
        float2 w4 = cmul(w2, w2);
        float2 w8 = cmul(w4, w4);
        float2 w16 = cmul(w8, w8);
        float2 base[4] = { make_float2(1.0f, 0.0f), w8, w16, cmul(w16, w8) };
        #pragma unroll
        for (int q = 0; q < 4; q++) {
            float2 wc = base[q];
            #pragma unroll
            for (int j = 0; j < 8; j++) {
                int c2 = 8 * q + j;
                r[brev5(c2)] = cmul(r[brev5(c2)], wc);
                wc = cmul(wc, wstep);
            }
        }
    }

    // ---- transpose: lane u=n2 -> lane u=k1
    float* sx = Sx[w];
    float* sy = Sy[w];
    #pragma unroll
    for (int i = 0; i < 32; i++) {
        int k1 = brev5(i);
        sx[k1 * 33 + u] = r[i].x;
        sy[k1 * 33 + u] = r[i].y;
    }
    __syncwarp();
    #pragma unroll
    for (int j = 0; j < 32; j++) {
        r[j].x = sx[u * 33 + j];
        r[j].y = sy[u * 33 + j];
    }
    __syncwarp();

    // ---- second FFT: r[i] = Z[u + 32*brev5(i)]
    fft32(r);

    // ---- untangle + LN + direct stores, natural k1 order (kk)
    float* orow = out + (size_t)row * CDIM;
    float2 uk;
    {
        float s, c;
        sincospif((float)u * (1.0f / 1024.0f), &s, &c);
        uk = make_float2(c, -s);                     // U[u]
    }
    const float2 W32 = make_float2(0.99518473f, -0.09801714f);  // exp(-i pi/32)
    #pragma unroll
    for (int kk = 0; kk < 32; kk++) {
        const int i = brev5(kk);
        float2 Zk = r[i];
        float zmx = __shfl_sync(FULL, r[31 - i].x, pux);
        float zmy = __shfl_sync(FULL, r[31 - i].y, pux);
        if (u == 0) {
            int i0 = brev5((32 - kk) & 31);
            zmx = r[i0].x;
            zmy = r[i0].y;
        }
        float ReE = 0.5f * (Zk.x + zmx);
        float ReO = 0.5f * (Zk.y + zmy);
        float ImO = -0.5f * (Zk.x - zmx);
        float yk = ReE + uk.x * ReO - uk.y * ImO;
        float zn = (yk - mu) * rs;
        int k = u + (kk << 5);
        orow[k] = zn * __ldg(gamma + k) + __ldg(beta + k);
        if (k > 0) {
            orow[2048 - k] = zn * __ldg(gamma + 2048 - k) + __ldg(beta + 2048 - k);
        } else {
            float y1024 = Zk.x - Zk.y;               // Z[0]: ReZ0 - ImZ0
            float zn2 = (y1024 - mu) * rs;
            orow[1024] = zn2 * __ldg(gamma + 1024) + __ldg(beta + 1024);
        }
        uk = cmul(uk, W32);
    }
}

// ---------------------------------------------------------------- launch
extern "C" void kernel_launch(void* const* d_in, const int* in_sizes, int n_in,
                              void* d_out, int out_size) {
    const float* x     = (const float*)d_in[0];
    const float* gamma = (const float*)d_in[1];
    const float* beta  = (const float*)d_in[2];
    float* out = (float*)d_out;

    fft_ln_kernel<<<ROWS / 4, 128>>>(x, gamma, beta, out);
}

// round 15
// speedup vs baseline: 1.1804x; 1.1804x over previous
#include <cuda_runtime.h>
#include <math.h>
#include <stdint.h>

// out = LayerNorm(Re(FFT(x, axis=-1))), x: (4,4096,2048) fp32.
// Pack z[n] = x[2n] + i x[2n+1] (1024 complex). 4-step CT: 1024 = 32 x 32,
// one WARP per row, 32 complex per lane:
//   FFT32 (regs) -> twiddle W_1024^{u k1} (register recurrence) -> smem
//   transpose (pad 33) -> FFT32 (regs): r[i] = Z[u + 32*brev5(i)]
// Paired untangle over kk=0..15 (k = u+32kk in [0,512)):
//   y[k]      = ReE + cos(pi k/1024) ReO + sin(pi k/1024) ImO
//   y[1024-k] = 2*ReE - y[k]          (shared E/O, angle reflection)
//   kk=0 pair IS y[1024]; y[512] = Re Z[512] = r[1].x on lane 0.
//   ssq accumulated in-loop; (y1, ReE) staged in transpose smem; after the
//   warp reduce, rescan + store 4 mirrored regions per kk (all coalesced).
// mu = x[0] exactly. No tables, no extra kernel, no __syncthreads.

#define ROWS 16384
#define CDIM 2048
#define EPS  1e-5f
#define FULL 0xffffffffu

__device__ __forceinline__ float2 cmul(float2 a, float2 b) {
    return make_float2(fmaf(a.x, b.x, -a.y * b.y), fmaf(a.x, b.y, a.y * b.x));
}

__host__ __device__ constexpr int brev5(int i) {
    return ((i & 1) << 4) | ((i & 2) << 2) | (i & 4) | ((i & 8) >> 2) | ((i & 16) >> 4);
}

// 32-pt DIF FFT (Gentleman-Sande), output bit-reversed: r[i] = X[brev5(i)].
__device__ __forceinline__ void fft32(float2* r) {
    const float CR[16] = { 1.0f, 0.98078528f, 0.92387953f, 0.83146961f,
                           0.70710678f, 0.55557023f, 0.38268343f, 0.19509032f,
                           0.0f, -0.19509032f, -0.38268343f, -0.55557023f,
                           -0.70710678f, -0.83146961f, -0.92387953f, -0.98078528f };
    const float CI[16] = { 0.0f, -0.19509032f, -0.38268343f, -0.55557023f,
                           -0.70710678f, -0.83146961f, -0.92387953f, -0.98078528f,
                           -1.0f, -0.98078528f, -0.92387953f, -0.83146961f,
                           -0.70710678f, -0.55557023f, -0.38268343f, -0.19509032f };
    #pragma unroll
    for (int half = 16; half >= 1; half >>= 1) {
        #pragma unroll
        for (int g = 0; g < 32; g += 2 * half) {
            #pragma unroll
            for (int j = 0; j < half; j++) {
                float2 a = r[g + j], b = r[g + j + half];
                r[g + j] = make_float2(a.x + b.x, a.y + b.y);
                float dx = a.x - b.x, dy = a.y - b.y;
                int tw = j * (16 / half);
                if (tw == 0) r[g + j + half] = make_float2(dx, dy);
                else r[g + j + half] = make_float2(fmaf(dx, CR[tw], -dy * CI[tw]),
                                                   fmaf(dx, CI[tw],  dy * CR[tw]));
            }
        }
    }
}

__global__ void __launch_bounds__(128, 4) fft_ln_kernel(const float* __restrict__ x,
                                                        const float* __restrict__ gamma,
                                                        const float* __restrict__ beta,
                                                        float* __restrict__ out) {
    __shared__ float Sx[4][33 * 32];
    __shared__ float Sy[4][33 * 32];

    const int t = threadIdx.x;
    const int w = t >> 5;
    const int u = t & 31;
    const int row = blockIdx.x * 4 + w;
    const float2* z = (const float2*)(x + (size_t)row * CDIM);

    float2 r[32];
    #pragma unroll
    for (int j = 0; j < 32; j++) r[j] = z[u + 32 * j];
    const float mu = __shfl_sync(FULL, r[0].x, 0);

    // ---- first FFT
    fft32(r);

    // ---- twiddle r[brev5(c)] *= W_1024^{u*c}; wstep = exp(-i pi u/512)
    {
        float s, c;
        sincospif((float)u * (1.0f / 512.0f), &s, &c);
        float2 wstep = make_float2(c, -s);
        float2 w2 = cmul(wstep, wstep);
        float2 w4 = cmul(w2, w2);
        float2 w8 = cmul(w4, w4);
        float2 w16 = cmul(w8, w8);
        float2 base[4] = { make_float2(1.0f, 0.0f), w8, w16, cmul(w16, w8) };
        #pragma unroll
        for (int q = 0; q < 4; q++) {
            float2 wc = base[q];
            #pragma unroll
            for (int j = 0; j < 8; j++) {
                int c2 = 8 * q + j;
                r[brev5(c2)] = cmul(r[brev5(c2)], wc);
                wc = cmul(wc, wstep);
            }
        }
    }

    // ---- transpose: lane u=n2 -> lane u=k1
    float* sx = Sx[w];
    float* sy = Sy[w];
    #pragma unroll
    for (int i = 0; i < 32; i++) {
        int k1 = brev5(i);
        sx[k1 * 33 + u] = r[i].x;
        sy[k1 * 33 + u] = r[i].y;
    }
    __syncwarp();
    #pragma unroll
    for (int j = 0; j < 32; j++) {
        r[j].x = sx[u * 33 + j];
        r[j].y = sy[u * 33 + j];
    }
    __syncwarp();

    // ---- second FFT: r[i] = Z[u + 32*brev5(i)]
    fft32(r);

    // ---- paired untangle, ssq in-loop, (y1, ReE) staged in smem
    const int pux = (32 - u) & 31;
    float ssq = 0.0f;
    float y0v = 0.0f, y1024v = 0.0f;
    float2 uk;
    {
        float s, c;
        sincospif((float)u * (1.0f / 1024.0f), &s, &c);
        uk = make_float2(c, -s);                     // U[u] = (cos, -sin)
    }
    const float2 W32 = make_float2(0.99518473f, -0.09801714f);  // exp(-i pi/32)
    #pragma unroll
    for (int kk = 0; kk < 16; kk++) {
        const int i = brev5(kk);
        float2 Zk = r[i];
        float zmx = __shfl_sync(FULL, r[31 - i].x, pux);
        float zmy = __shfl_sync(FULL, r[31 - i].y, pux);
        if (u == 0) {
            int i0 = brev5((32 - kk) & 31);
            zmx = r[i0].x;
            zmy = r[i0].y;
        }
        float ReE = 0.5f * (Zk.x + zmx);
        float ReO = 0.5f * (Zk.y + zmy);
        float ImO = -0.5f * (Zk.x - zmx);
        float y1 = ReE + uk.x * ReO - uk.y * ImO;    // y[k]
        float y2 = 2.0f * ReE - y1;                  // y[1024-k]
        sx[kk * 33 + u] = y1;
        sy[kk * 33 + u] = ReE;
        ssq += 2.0f * (y1 * y1 + y2 * y2);
        if (kk == 0 && u == 0) { y0v = y1; y1024v = y2; }
        uk = cmul(uk, W32);
    }
    if (u == 0) {
        float y512 = r[1].x;                         // Z[512] real (ImO=0, cos=0)
        ssq += 2.0f * y512 * y512 - y0v * y0v - y1024v * y1024v;
    }

    #pragma unroll
    for (int o = 16; o > 0; o >>= 1) ssq += __shfl_xor_sync(FULL, ssq, o);
    const float rs = rsqrtf(ssq * (1.0f / 2048.0f) - mu * mu + EPS);

    // ---- scaled stores: 4 mirrored regions per kk, all coalesced
    float* orow = out + (size_t)row * CDIM;
    #pragma unroll
    for (int kk = 0; kk < 16; kk++) {
        float y1 = sx[kk * 33 + u];
        float y2 = 2.0f * sy[kk * 33 + u] - y1;
        int k = u + (kk << 5);
        float zn1 = (y1 - mu) * rs;
        float zn2 = (y2 - mu) * rs;
        orow[k] = zn1 * __ldg(gamma + k) + __ldg(beta + k);
        if (k > 0)
            orow[2048 - k] = zn1 * __ldg(gamma + 2048 - k) + __ldg(beta + 2048 - k);
        orow[1024 - k] = zn2 * __ldg(gamma + 1024 - k) + __ldg(beta + 1024 - k);
        if (k > 0)
            orow[1024 + k] = zn2 * __ldg(gamma + 1024 + k) + __ldg(beta + 1024 + k);
    }
    if (u == 0) {
        float zn = (r[1].x - mu) * rs;
        orow[512]  = zn * __ldg(gamma + 512)  + __ldg(beta + 512);
        orow[1536] = zn * __ldg(gamma + 1536) + __ldg(beta + 1536);
    }
}

// ---------------------------------------------------------------- launch
extern "C" void kernel_launch(void* const* d_in, const int* in_sizes, int n_in,
                              void* d_out, int out_size) {
    const float* x     = (const float*)d_in[0];
    const float* gamma = (const float*)d_in[1];
    const float* beta  = (const float*)d_in[2];
    float* out = (float*)d_out;

    fft_ln_kernel<<<ROWS / 4, 128>>>(x, gamma, beta, out);
}

// round 16
// speedup vs baseline: 1.4294x; 1.2110x over previous
#include <cuda_runtime.h>
#include <math.h>
#include <stdint.h>

// out = LayerNorm(Re(FFT(x, axis=-1))), x: (4,4096,2048) fp32.
// Pack z[n] = x[2n] + i x[2n+1] (1024 complex). 4-step CT: 1024 = 32 x 32,
// one WARP per row, 32 complex per lane:
//   FFT32 (regs, packed f32x2 add/sub) -> twiddle W_1024^{u k1} (register
//   recurrence) -> smem transpose (pad 33) -> FFT32: r[i] = Z[u+32*brev5(i)]
// Paired untangle over kk=0..15 (k = u+32kk in [0,512)):
//   y[k]      = ReE + cos(pi k/1024) ReO + sin(pi k/1024) ImO
//   y[1024-k] = 2*ReE - y[k]
//   (y1, ReE) written back into the DEAD register r[brev5(kk)] (liveness:
//   iteration kk touches only r[i], r[31-i], identical indices in all lanes,
//   disjoint across iterations) -> rescan is register-only.
//   kk=0 pair IS y[1024]; y[512] = Re Z[512] = r[1].x on lane 0 (odd reg,
//   never overwritten). mu = x[0] exactly. No tables, no __syncthreads.

#define ROWS 16384
#define CDIM 2048
#define EPS  1e-5f
#define FULL 0xffffffffu

__device__ __forceinline__ float2 cmul(float2 a, float2 b) {
    return make_float2(fmaf(a.x, b.x, -a.y * b.y), fmaf(a.x, b.y, a.y * b.x));
}
__device__ __forceinline__ float2 fadd2(float2 a, float2 b) {
    unsigned long long ra, rb, rc;
    ra = *(unsigned long long*)&a;
    rb = *(unsigned long long*)&b;
    asm("add.rn.f32x2 %0, %1, %2;" : "=l"(rc) : "l"(ra), "l"(rb));
    return *(float2*)&rc;
}
__device__ __forceinline__ float2 fsub2(float2 a, float2 b) {
    unsigned long long ra, rb, rc;
    ra = *(unsigned long long*)&a;
    rb = *(unsigned long long*)&b;
    asm("sub.rn.f32x2 %0, %1, %2;" : "=l"(rc) : "l"(ra), "l"(rb));
    return *(float2*)&rc;
}

__host__ __device__ constexpr int brev5(int i) {
    return ((i & 1) << 4) | ((i & 2) << 2) | (i & 4) | ((i & 8) >> 2) | ((i & 16) >> 4);
}

// 32-pt DIF FFT (Gentleman-Sande), output bit-reversed: r[i] = X[brev5(i)].
__device__ __forceinline__ void fft32(float2* r) {
    const float CR[16] = { 1.0f, 0.98078528f, 0.92387953f, 0.83146961f,
                           0.70710678f, 0.55557023f, 0.38268343f, 0.19509032f,
                           0.0f, -0.19509032f, -0.38268343f, -0.55557023f,
                           -0.70710678f, -0.83146961f, -0.92387953f, -0.98078528f };
    const float CI[16] = { 0.0f, -0.19509032f, -0.38268343f, -0.55557023f,
                           -0.70710678f, -0.83146961f, -0.92387953f, -0.98078528f,
                           -1.0f, -0.98078528f, -0.92387953f, -0.83146961f,
                           -0.70710678f, -0.55557023f, -0.38268343f, -0.19509032f };
    #pragma unroll
    for (int half = 16; half >= 1; half >>= 1) {
        #pragma unroll
        for (int g = 0; g < 32; g += 2 * half) {
            #pragma unroll
            for (int j = 0; j < half; j++) {
                float2 a = r[g + j], b = r[g + j + half];
                r[g + j] = fadd2(a, b);
                float2 d = fsub2(a, b);
                int tw = j * (16 / half);
                if (tw == 0) r[g + j + half] = d;
                else r[g + j + half] = make_float2(fmaf(d.x, CR[tw], -d.y * CI[tw]),
                                                   fmaf(d.x, CI[tw],  d.y * CR[tw]));
            }
        }
    }
}

__global__ void __launch_bounds__(128, 4) fft_ln_kernel(const float* __restrict__ x,
                                                        const float* __restrict__ gamma,
                                                        const float* __restrict__ beta,
                                                        float* __restrict__ out) {
    __shared__ float Sx[4][33 * 32];
    __shared__ float Sy[4][33 * 32];

    const int t = threadIdx.x;
    const int w = t >> 5;
    const int u = t & 31;
    const int row = blockIdx.x * 4 + w;
    const float2* z = (const float2*)(x + (size_t)row * CDIM);

    float2 r[32];
    #pragma unroll
    for (int j = 0; j < 32; j++) r[j] = z[u + 32 * j];
    const float mu = __shfl_sync(FULL, r[0].x, 0);

    // ---- first FFT
    fft32(r);

    // ---- twiddle r[brev5(c)] *= W_1024^{u*c}; wstep = exp(-i pi u/512)
    {
        float s, c;
        sincospif((float)u * (1.0f / 512.0f), &s, &c);
        float2 wstep = make_float2(c, -s);
        float2 w2 = cmul(wstep, wstep);
        float2 w4 = cmul(w2, w2);
        float2 w8 = cmul(w4, w4);
        float2 w16 = cmul(w8, w8);
        float2 base[4] = { make_float2(1.0f, 0.0f), w8, w16, cmul(w16, w8) };
        #pragma unroll
        for (int q = 0; q < 4; q++) {
            float2 wc = base[q];
            #pragma unroll
            for (int j = 0; j < 8; j++) {
                int c2 = 8 * q + j;
                r[brev5(c2)] = cmul(r[brev5(c2)], wc);
                wc = cmul(wc, wstep);
            }
        }
    }

    // ---- transpose: lane u=n2 -> lane u=k1
    float* sx = Sx[w];
    float* sy = Sy[w];
    #pragma unroll
    for (int i = 0; i < 32; i++) {
        int k1 = brev5(i);
        sx[k1 * 33 + u] = r[i].x;
        sy[k1 * 33 + u] = r[i].y;
    }
    __syncwarp();
    #pragma unroll
    for (int j = 0; j < 32; j++) {
        r[j].x = sx[u * 33 + j];
        r[j].y = sy[u * 33 + j];
    }
    __syncwarp();

    // ---- second FFT: r[i] = Z[u + 32*brev5(i)]
    fft32(r);

    // ---- paired untangle; (y1, ReE) overwrite the dead register r[i]
    const int pux = (32 - u) & 31;
    float ssq = 0.0f;
    float y0v = 0.0f, y1024v = 0.0f;
    float2 uk;
    {
        float s, c;
        sincospif((float)u * (1.0f / 1024.0f), &s, &c);
        uk = make_float2(c, -s);                     // U[u] = (cos, -sin)
    }
    const float2 W32 = make_float2(0.99518473f, -0.09801714f);  // exp(-i pi/32)
    #pragma unroll
    for (int kk = 0; kk < 16; kk++) {
        const int i = brev5(kk);
        float2 Zk = r[i];
        float zmx = __shfl_sync(FULL, r[31 - i].x, pux);
        float zmy = __shfl_sync(FULL, r[31 - i].y, pux);
        if (u == 0) {
            int i0 = brev5((32 - kk) & 31);          // kk=0 -> 0 (pre-write read); else odd
            zmx = r[i0].x;
            zmy = r[i0].y;
        }
        float ReE = 0.5f * (Zk.x + zmx);
        float ReO = 0.5f * (Zk.y + zmy);
        float ImO = -0.5f * (Zk.x - zmx);
        float y1 = ReE + uk.x * ReO - uk.y * ImO;    // y[k]
        float y2 = 2.0f * ReE - y1;                  // y[1024-k]
        r[i] = make_float2(y1, ReE);                 // register staging
        ssq += 2.0f * (y1 * y1 + y2 * y2);
        if (kk == 0 && u == 0) { y0v = y1; y1024v = y2; }
        uk = cmul(uk, W32);
    }
    if (u == 0) {
        float y512 = r[1].x;                         // Z[512] real; odd reg, intact
        ssq += 2.0f * y512 * y512 - y0v * y0v - y1024v * y1024v;
    }

    #pragma unroll
    for (int o = 16; o > 0; o >>= 1) ssq += __shfl_xor_sync(FULL, ssq, o);
    const float rs = rsqrtf(ssq * (1.0f / 2048.0f) - mu * mu + EPS);

    // ---- scaled stores: 4 mirrored regions per kk, register-only rescan
    float* orow = out + (size_t)row * CDIM;
    #pragma unroll
    for (int kk = 0; kk < 16; kk++) {
        const int i = brev5(kk);
        float y1 = r[i].x;
        float y2 = 2.0f * r[i].y - y1;
        int k = u + (kk << 5);
        float zn1 = (y1 - mu) * rs;
        float zn2 = (y2 - mu) * rs;
        orow[k] = zn1 * __ldg(gamma + k) + __ldg(beta + k);
        if (k > 0)
            orow[2048 - k] = zn1 * __ldg(gamma + 2048 - k) + __ldg(beta + 2048 - k);
        orow[1024 - k] = zn2 * __ldg(gamma + 1024 - k) + __ldg(beta + 1024 - k);
        if (k > 0)
            orow[1024 + k] = zn2 * __ldg(gamma + 1024 + k) + __ldg(beta + 1024 + k);
    }
    if (u == 0) {
        float zn = (r[1].x - mu) * rs;
        orow[512]  = zn * __ldg(gamma + 512)  + __ldg(beta + 512);
        orow[1536] = zn * __ldg(gamma + 1536) + __ldg(beta + 1536);
    }
}

// ---------------------------------------------------------------- launch
extern "C" void kernel_launch(void* const* d_in, const int* in_sizes, int n_in,
                              void* d_out, int out_size) {
    const float* x     = (const float*)d_in[0];
    const float* gamma = (const float*)d_in[1];
    const float* beta  = (const float*)d_in[2];
    float* out = (float*)d_out;

    fft_ln_kernel<<<ROWS / 4, 128>>>(x, gamma, beta, out);
}